// round 7
// baseline (speedup 1.0000x reference)
#include <cuda_runtime.h>
#include <cuda_bf16.h>

// Problem constants (dataset fixed; runtime values clamped to these).
#define NMAX   100000
#define EMAX   1250000
#define DIM    64
#define NGRAPH 512
#define SCAN_BLK 1024
#define NB_MAX   128    // ceil(NMAX/SCAN_BLK) = 98 <= 128

// ---------------- scratch (__device__ globals; allocation-free rule) -------
__device__ float4 g_agg  [NMAX   * (DIM / 4)];   // 25.6 MB
__device__ float4 g_h    [NMAX   * (DIM / 4)];   // 25.6 MB
__device__ float4 g_pool [NGRAPH * (DIM / 4)];
__device__ float4 g_cnt4 [NGRAPH / 4];
// CSR scratch
__device__ int   g_deg   [NMAX];
__device__ int   g_cursor[NMAX];
__device__ int   g_off   [NMAX + 1];
__device__ int   g_flag  [NB_MAX];     // chained-scan ready flags
__device__ int   g_incl  [NB_MAX];     // chained-scan inclusive block prefixes
__device__ int   g_psrc  [EMAX];
__device__ float g_pw    [EMAX];

// ---------------------------------------------------------------------------
__device__ __forceinline__ void red_add_v4(float4* addr, float4 v) {
    asm volatile("red.global.add.v4.f32 [%0], {%1, %2, %3, %4};"
                 :: "l"(addr), "f"(v.x), "f"(v.y), "f"(v.z), "f"(v.w)
                 : "memory");
}
__device__ __forceinline__ void red_add_f32(float* addr, float v) {
    asm volatile("red.global.add.f32 [%0], %1;"
                 :: "l"(addr), "f"(v) : "memory");
}
__device__ __forceinline__ int guard_idx(int i, int n) {
    return ((unsigned)i < (unsigned)n) ? i : 0;
}

// ---------------------------------------------------------------------------
// Fused init: zero deg, scan flags, pool, counts in ONE launch.
// ---------------------------------------------------------------------------
__global__ void init_kernel(int N) {
    int i = blockIdx.x * blockDim.x + threadIdx.x;
    if (i < N) g_deg[i] = 0;
    if (i < NB_MAX) { g_flag[i] = 0; g_incl[i] = 0; }
    if (i < NGRAPH * 16) g_pool[i] = make_float4(0.f, 0.f, 0.f, 0.f);
    if (i < NGRAPH / 4)  g_cnt4[i] = make_float4(0.f, 0.f, 0.f, 0.f);
}

// ---------------------------------------------------------------------------
// Degree histogram
// ---------------------------------------------------------------------------
__global__ void hist_kernel(const int* __restrict__ dst, int E, int N) {
    int e = blockIdx.x * blockDim.x + threadIdx.x;
    if (e < E) atomicAdd(&g_deg[guard_idx(dst[e], N)], 1);
}

// ---------------------------------------------------------------------------
// Single-pass exclusive scan (chained blocks with spin-on-flag lookback).
// nb = 98 blocks <= 148 SMs: all co-resident, so the chain cannot deadlock.
// Also seeds g_cursor = g_off so fill_kernel needs only one atomicAdd.
// ---------------------------------------------------------------------------
__global__ __launch_bounds__(SCAN_BLK)
void scan_kernel(int N) {
    __shared__ int s[SCAN_BLK];
    __shared__ int sh_prev;
    int tx = threadIdx.x;
    int bid = blockIdx.x;
    int i = bid * SCAN_BLK + tx;
    int v = (i < N) ? g_deg[i] : 0;
    s[tx] = v;
    __syncthreads();
    for (int d = 1; d < SCAN_BLK; d <<= 1) {
        int t = (tx >= d) ? s[tx - d] : 0;
        __syncthreads();
        s[tx] += t;
        __syncthreads();
    }
    if (tx == 0) {
        int total = s[SCAN_BLK - 1];
        int prev = 0;
        if (bid > 0) {
            volatile int* vf = g_flag;
            while (vf[bid - 1] == 0) { }
            __threadfence();
            prev = *((volatile int*)&g_incl[bid - 1]);
        }
        g_incl[bid] = prev + total;
        __threadfence();
        *((volatile int*)&g_flag[bid]) = 1;
        sh_prev = prev;
    }
    __syncthreads();
    int prev = sh_prev;
    if (i < N) {
        int excl = prev + s[tx] - v;
        g_off[i] = excl;
        g_cursor[i] = excl;
    }
    // last thread of last block writes off[N] (= total edge count)
    if (bid == gridDim.x - 1 && tx == SCAN_BLK - 1)
        g_off[N] = prev + s[tx];
}

// ---------------------------------------------------------------------------
// Bucket fill: one atomicAdd on the pre-seeded cursor gives the slot.
// ---------------------------------------------------------------------------
__global__ void fill_kernel(const int* __restrict__ src, const int* __restrict__ dst,
                            const float* __restrict__ w, int E, int N) {
    int e = blockIdx.x * blockDim.x + threadIdx.x;
    if (e >= E) return;
    int d = guard_idx(dst[e], N);
    int slot = atomicAdd(&g_cursor[d], 1);
    g_psrc[slot] = guard_idx(src[e], N);
    g_pw[slot]   = w[e];
}

// ---------------------------------------------------------------------------
// CSR aggregation: one warp per dst row; half-warp h walks edges beg+h,
// beg+h+2, ...; lane j owns float4 column j (256B coalesced gather/edge).
// Manual 2-way unroll keeps two independent gather chains in flight.
// ---------------------------------------------------------------------------
__global__ __launch_bounds__(256)
void agg_csr_kernel(const float4* __restrict__ feat,
                    float4* __restrict__ agg, int N) {
    int warp = (blockIdx.x * blockDim.x + threadIdx.x) >> 5;
    if (warp >= N) return;
    int lane = threadIdx.x & 31;
    int half = lane >> 4;
    int j = lane & 15;

    int beg = g_off[warp];
    int end = g_off[warp + 1];

    float4 a0 = make_float4(0.f, 0.f, 0.f, 0.f);
    float4 a1 = make_float4(0.f, 0.f, 0.f, 0.f);
    int i = beg + half;
    for (; i + 2 < end; i += 4) {
        int   s0 = g_psrc[i],  s1 = g_psrc[i + 2];
        float w0 = g_pw[i],    w1 = g_pw[i + 2];
        float4 v0 = feat[(size_t)s0 * 16 + j];
        float4 v1 = feat[(size_t)s1 * 16 + j];
        a0.x = fmaf(v0.x, w0, a0.x);  a1.x = fmaf(v1.x, w1, a1.x);
        a0.y = fmaf(v0.y, w0, a0.y);  a1.y = fmaf(v1.y, w1, a1.y);
        a0.z = fmaf(v0.z, w0, a0.z);  a1.z = fmaf(v1.z, w1, a1.z);
        a0.w = fmaf(v0.w, w0, a0.w);  a1.w = fmaf(v1.w, w1, a1.w);
    }
    if (i < end) {
        int   s0 = g_psrc[i];
        float w0 = g_pw[i];
        float4 v0 = feat[(size_t)s0 * 16 + j];
        a0.x = fmaf(v0.x, w0, a0.x);
        a0.y = fmaf(v0.y, w0, a0.y);
        a0.z = fmaf(v0.z, w0, a0.z);
        a0.w = fmaf(v0.w, w0, a0.w);
    }
    a0.x += a1.x; a0.y += a1.y; a0.z += a1.z; a0.w += a1.w;
    a0.x += __shfl_xor_sync(0xffffffffu, a0.x, 16);
    a0.y += __shfl_xor_sync(0xffffffffu, a0.y, 16);
    a0.z += __shfl_xor_sync(0xffffffffu, a0.z, 16);
    a0.w += __shfl_xor_sync(0xffffffffu, a0.w, 16);
    if (half == 0) agg[(size_t)warp * 16 + j] = a0;
}

// ---------------------------------------------------------------------------
// Fused node transform: out = leaky_relu(agg @ W_rel + x @ W_root + b)
// Software-pipelined global loads: iteration kk+1's x/agg float4s are issued
// before iteration kk's 128-FMA body, hiding the ~250cyc L2 latency.
// MODE 0: write rows. MODE 1: fused mean-pool accumulation (red.v4).
// ---------------------------------------------------------------------------
template <int MODE>
__global__ __launch_bounds__(128)
void node_gemm_kernel(const float4* __restrict__ xin,
                      const float4* __restrict__ agg,
                      const float*  __restrict__ Wroot,
                      const float*  __restrict__ Wrel,
                      const float*  __restrict__ bias,
                      float4* __restrict__ out,
                      const int* __restrict__ batch,
                      int Nn) {
    __shared__ float4 sWr[64 * 16];
    __shared__ float4 sWe[64 * 16];
    __shared__ float  sb[64];

    const float4* Wr4 = (const float4*)Wroot;
    const float4* We4 = (const float4*)Wrel;
    for (int i = threadIdx.x; i < 1024; i += 128) {
        sWr[i] = Wr4[i];
        sWe[i] = We4[i];
    }
    if (threadIdx.x < 64) sb[threadIdx.x] = bias[threadIdx.x];
    __syncthreads();

    int n = blockIdx.x * 128 + threadIdx.x;
    if (n >= Nn) return;

    float acc[64];
#pragma unroll
    for (int j = 0; j < 64; j++) acc[j] = sb[j];

    const float4* xr = xin + (size_t)n * 16;
    const float4* ar = agg + (size_t)n * 16;

    float4 xv = xr[0];
    float4 av = ar[0];
#pragma unroll 1
    for (int kk = 0; kk < 16; kk++) {
        int nxt = (kk + 1) & 15;            // last prefetch wraps (harmless)
        float4 xn = xr[nxt];
        float4 an = ar[nxt];
#pragma unroll
        for (int dk = 0; dk < 4; dk++) {
            float xs = (&xv.x)[dk];
            float as = (&av.x)[dk];
            int k = 4 * kk + dk;
#pragma unroll
            for (int jj = 0; jj < 16; jj++) {
                float4 wv = sWr[k * 16 + jj];
                float4 ev = sWe[k * 16 + jj];
                acc[4 * jj + 0] = fmaf(xs, wv.x, fmaf(as, ev.x, acc[4 * jj + 0]));
                acc[4 * jj + 1] = fmaf(xs, wv.y, fmaf(as, ev.y, acc[4 * jj + 1]));
                acc[4 * jj + 2] = fmaf(xs, wv.z, fmaf(as, ev.z, acc[4 * jj + 2]));
                acc[4 * jj + 3] = fmaf(xs, wv.w, fmaf(as, ev.w, acc[4 * jj + 3]));
            }
        }
        xv = xn;
        av = an;
    }

#pragma unroll
    for (int j = 0; j < 64; j++) {
        float v = acc[j];
        acc[j] = v > 0.f ? v : 0.01f * v;
    }

    if (MODE == 0) {
        float4* o = out + (size_t)n * 16;
#pragma unroll
        for (int jj = 0; jj < 16; jj++)
            o[jj] = make_float4(acc[4 * jj + 0], acc[4 * jj + 1],
                                acc[4 * jj + 2], acc[4 * jj + 3]);
    } else {
        int b = guard_idx(batch[n], NGRAPH);
        float4* pr = g_pool + (size_t)b * 16;
#pragma unroll
        for (int jj = 0; jj < 16; jj++)
            red_add_v4(&pr[jj], make_float4(acc[4 * jj + 0], acc[4 * jj + 1],
                                            acc[4 * jj + 2], acc[4 * jj + 3]));
        red_add_f32(((float*)g_cnt4) + b, 1.0f);
    }
}

// ---------------------------------------------------------------------------
// Final: out[g] = (pool[g] / max(cnt[g],1)) @ Wl + bl     (512 x 64 x 8)
// ---------------------------------------------------------------------------
__global__ void final_kernel(const float* __restrict__ Wl,
                             const float* __restrict__ bl,
                             float* __restrict__ out) {
    __shared__ float sW[64 * 8];
    __shared__ float sb2[8];
    int t = threadIdx.x;                 // blockDim.x == 512
    sW[t] = Wl[t];
    if (t < 8) sb2[t] = bl[t];
    __syncthreads();

    int g = t;
    float cnt = ((const float*)g_cnt4)[g];
    float inv = 1.0f / fmaxf(cnt, 1.0f);
    const float* pr = (const float*)(g_pool + (size_t)g * 16);

    float acc[8];
#pragma unroll
    for (int j = 0; j < 8; j++) acc[j] = sb2[j];
#pragma unroll 4
    for (int k = 0; k < 64; k++) {
        float p = pr[k] * inv;
#pragma unroll
        for (int j = 0; j < 8; j++)
            acc[j] = fmaf(p, sW[k * 8 + j], acc[j]);
    }
#pragma unroll
    for (int j = 0; j < 8; j++) out[g * 8 + j] = acc[j];
}

// ---------------------------------------------------------------------------
// Launch sequence (graph-capturable: kernels only)
// ---------------------------------------------------------------------------
extern "C" void kernel_launch(void* const* d_in, const int* in_sizes, int n_in,
                              void* d_out, int out_size) {
    const float4* x      = (const float4*)d_in[0];
    const int*    ei     = (const int*)d_in[1];     // [2, E] int32
    const float*  w      = (const float*)d_in[2];
    const int*    batch  = (const int*)d_in[3];     // int32
    const float*  W1root = (const float*)d_in[4];
    const float*  W1rel  = (const float*)d_in[5];
    const float*  b1     = (const float*)d_in[6];
    const float*  W2root = (const float*)d_in[7];
    const float*  W2rel  = (const float*)d_in[8];
    const float*  b2     = (const float*)d_in[9];
    const float*  Wl     = (const float*)d_in[10];
    const float*  bl     = (const float*)d_in[11];
    float*        out    = (float*)d_out;

    int N = in_sizes[0] / DIM;        // 100000
    int E = in_sizes[2];              // 1250000
    if (N > NMAX) N = NMAX;
    if (E > EMAX) E = EMAX;
    const int* src = ei;
    const int* dst = ei + E;

    float4 *agg, *h;
    cudaGetSymbolAddress((void**)&agg, g_agg);
    cudaGetSymbolAddress((void**)&h,   g_h);

    int nb      = (N + SCAN_BLK - 1) / SCAN_BLK;       // 98
    int eBlk    = (E + 255) / 256;
    int nBlk    = (N + 255) / 256;
    int gemmBlk = (N + 127) / 128;
    int aggBlk  = (N + 7) / 8;                         // 8 warps / block

    // ---- CSR build (once; shared by both layers) + all scratch zeroing ----
    init_kernel<<<nBlk, 256>>>(N);
    hist_kernel<<<eBlk, 256>>>(dst, E, N);
    scan_kernel<<<nb, SCAN_BLK>>>(N);
    fill_kernel<<<eBlk, 256>>>(src, dst, w, E, N);

    // ---- Layer 1 ----
    agg_csr_kernel<<<aggBlk, 256>>>(x, agg, N);
    node_gemm_kernel<0><<<gemmBlk, 128>>>(x, agg, W1root, W1rel, b1,
                                          h, nullptr, N);
    // ---- Layer 2 (+ fused mean-pool accumulation) ----
    agg_csr_kernel<<<aggBlk, 256>>>(h, agg, N);
    node_gemm_kernel<1><<<gemmBlk, 128>>>(h, agg, W2root, W2rel, b2,
                                          nullptr, batch, N);
    // ---- Readout ----
    final_kernel<<<1, 512>>>(Wl, bl, out);
}

// round 8
// speedup vs baseline: 1.9261x; 1.9261x over previous
#include <cuda_runtime.h>
#include <cuda_bf16.h>

// Problem constants (dataset fixed; runtime values clamped to these).
#define NMAX   100000
#define EMAX   1250000
#define DIM    64
#define NGRAPH 512
#define SCAN_BLK 1024
#define NB_MAX   128    // ceil(NMAX/SCAN_BLK) = 98 <= 128

// ---------------- scratch (__device__ globals; allocation-free rule) -------
__device__ float4 g_agg  [NMAX   * (DIM / 4)];   // 25.6 MB
__device__ float4 g_h    [NMAX   * (DIM / 4)];   // 25.6 MB
__device__ float4 g_pool [NGRAPH * (DIM / 4)];
__device__ float4 g_cnt4 [NGRAPH / 4];
// CSR scratch
__device__ int   g_deg   [NMAX];
__device__ int   g_cursor[NMAX];
__device__ int   g_off   [NMAX + 1];
__device__ int   g_bsum  [NB_MAX];
__device__ int   g_boff  [NB_MAX];
__device__ int   g_psrc  [EMAX];
__device__ float g_pw    [EMAX];

// ---------------------------------------------------------------------------
__device__ __forceinline__ void red_add_v4(float4* addr, float4 v) {
    asm volatile("red.global.add.v4.f32 [%0], {%1, %2, %3, %4};"
                 :: "l"(addr), "f"(v.x), "f"(v.y), "f"(v.z), "f"(v.w)
                 : "memory");
}
__device__ __forceinline__ void red_add_f32(float* addr, float v) {
    asm volatile("red.global.add.f32 [%0], %1;"
                 :: "l"(addr), "f"(v) : "memory");
}
__device__ __forceinline__ int guard_idx(int i, int n) {
    return ((unsigned)i < (unsigned)n) ? i : 0;
}

// ---------------------------------------------------------------------------
// Fused init: zero deg, pool, counts in ONE launch.
// ---------------------------------------------------------------------------
__global__ void init_kernel(int N) {
    int i = blockIdx.x * blockDim.x + threadIdx.x;
    if (i < N) g_deg[i] = 0;
    if (i < NGRAPH * 16) g_pool[i] = make_float4(0.f, 0.f, 0.f, 0.f);
    if (i < NGRAPH / 4)  g_cnt4[i] = make_float4(0.f, 0.f, 0.f, 0.f);
}

// ---------------------------------------------------------------------------
// Degree histogram
// ---------------------------------------------------------------------------
__global__ void hist_kernel(const int* __restrict__ dst, int E, int N) {
    int e = blockIdx.x * blockDim.x + threadIdx.x;
    if (e < E) atomicAdd(&g_deg[guard_idx(dst[e], N)], 1);
}

// ---------------------------------------------------------------------------
// 3-phase exclusive scan (dependency depth = 3 kernels, NOT 98 blocks).
// The Round-7 decoupled-lookback chain cost ~2.5us per block hop x 97 hops;
// this structure does the same work in ~5us total.
// ---------------------------------------------------------------------------
__global__ void scanA_kernel(int* __restrict__ off, int N) {
    __shared__ int s[SCAN_BLK];
    int tx = threadIdx.x;
    int i = blockIdx.x * SCAN_BLK + tx;
    int v = (i < N) ? g_deg[i] : 0;
    s[tx] = v;
    __syncthreads();
    for (int d = 1; d < SCAN_BLK; d <<= 1) {
        int t = (tx >= d) ? s[tx - d] : 0;
        __syncthreads();
        s[tx] += t;
        __syncthreads();
    }
    if (i < N) off[i] = s[tx] - v;                 // exclusive within block
    if (tx == SCAN_BLK - 1) g_bsum[blockIdx.x] = s[tx];
}

__global__ void scanB_kernel(int nb, int* __restrict__ off_last, int E) {
    __shared__ int s[NB_MAX];
    int tx = threadIdx.x;                          // blockDim.x == NB_MAX
    int v = (tx < nb) ? g_bsum[tx] : 0;
    s[tx] = v;
    __syncthreads();
    for (int d = 1; d < NB_MAX; d <<= 1) {
        int t = (tx >= d) ? s[tx - d] : 0;
        __syncthreads();
        s[tx] += t;
        __syncthreads();
    }
    if (tx < nb) g_boff[tx] = s[tx] - v;
    if (tx == 0) *off_last = E;                    // off[N] = E
}

__global__ void scanC_kernel(int* __restrict__ off, int N) {
    int i = blockIdx.x * blockDim.x + threadIdx.x;
    if (i < N) {
        int o = off[i] + g_boff[i >> 10];
        off[i] = o;
        g_cursor[i] = o;        // seed cursor: fill needs only one atomicAdd
    }
}

// ---------------------------------------------------------------------------
// Bucket fill: one atomicAdd on the pre-seeded cursor gives the slot.
// ---------------------------------------------------------------------------
__global__ void fill_kernel(const int* __restrict__ src, const int* __restrict__ dst,
                            const float* __restrict__ w, int E, int N) {
    int e = blockIdx.x * blockDim.x + threadIdx.x;
    if (e >= E) return;
    int d = guard_idx(dst[e], N);
    int slot = atomicAdd(&g_cursor[d], 1);
    g_psrc[slot] = guard_idx(src[e], N);
    g_pw[slot]   = w[e];
}

// ---------------------------------------------------------------------------
// CSR aggregation: one warp per dst row; half-warp h walks edges beg+h,
// beg+h+2, ...; lane j owns float4 column j (256B coalesced gather/edge).
// Manual 2-way unroll keeps two independent gather chains in flight.
// ---------------------------------------------------------------------------
__global__ __launch_bounds__(256)
void agg_csr_kernel(const float4* __restrict__ feat,
                    float4* __restrict__ agg, int N) {
    int warp = (blockIdx.x * blockDim.x + threadIdx.x) >> 5;
    if (warp >= N) return;
    int lane = threadIdx.x & 31;
    int half = lane >> 4;
    int j = lane & 15;

    int beg = g_off[warp];
    int end = g_off[warp + 1];

    float4 a0 = make_float4(0.f, 0.f, 0.f, 0.f);
    float4 a1 = make_float4(0.f, 0.f, 0.f, 0.f);
    int i = beg + half;
    for (; i + 2 < end; i += 4) {
        int   s0 = g_psrc[i],  s1 = g_psrc[i + 2];
        float w0 = g_pw[i],    w1 = g_pw[i + 2];
        float4 v0 = feat[(size_t)s0 * 16 + j];
        float4 v1 = feat[(size_t)s1 * 16 + j];
        a0.x = fmaf(v0.x, w0, a0.x);  a1.x = fmaf(v1.x, w1, a1.x);
        a0.y = fmaf(v0.y, w0, a0.y);  a1.y = fmaf(v1.y, w1, a1.y);
        a0.z = fmaf(v0.z, w0, a0.z);  a1.z = fmaf(v1.z, w1, a1.z);
        a0.w = fmaf(v0.w, w0, a0.w);  a1.w = fmaf(v1.w, w1, a1.w);
    }
    if (i < end) {
        int   s0 = g_psrc[i];
        float w0 = g_pw[i];
        float4 v0 = feat[(size_t)s0 * 16 + j];
        a0.x = fmaf(v0.x, w0, a0.x);
        a0.y = fmaf(v0.y, w0, a0.y);
        a0.z = fmaf(v0.z, w0, a0.z);
        a0.w = fmaf(v0.w, w0, a0.w);
    }
    a0.x += a1.x; a0.y += a1.y; a0.z += a1.z; a0.w += a1.w;
    a0.x += __shfl_xor_sync(0xffffffffu, a0.x, 16);
    a0.y += __shfl_xor_sync(0xffffffffu, a0.y, 16);
    a0.z += __shfl_xor_sync(0xffffffffu, a0.z, 16);
    a0.w += __shfl_xor_sync(0xffffffffu, a0.w, 16);
    if (half == 0) agg[(size_t)warp * 16 + j] = a0;
}

// ---------------------------------------------------------------------------
// Fused node transform: out = leaky_relu(agg @ W_rel + x @ W_root + b)
// Software-pipelined global loads: iteration kk+1's x/agg float4s are issued
// before iteration kk's 128-FMA body, hiding the ~250cyc L2 latency.
// MODE 0: write rows. MODE 1: fused mean-pool accumulation (red.v4).
// ---------------------------------------------------------------------------
template <int MODE>
__global__ __launch_bounds__(128)
void node_gemm_kernel(const float4* __restrict__ xin,
                      const float4* __restrict__ agg,
                      const float*  __restrict__ Wroot,
                      const float*  __restrict__ Wrel,
                      const float*  __restrict__ bias,
                      float4* __restrict__ out,
                      const int* __restrict__ batch,
                      int Nn) {
    __shared__ float4 sWr[64 * 16];
    __shared__ float4 sWe[64 * 16];
    __shared__ float  sb[64];

    const float4* Wr4 = (const float4*)Wroot;
    const float4* We4 = (const float4*)Wrel;
    for (int i = threadIdx.x; i < 1024; i += 128) {
        sWr[i] = Wr4[i];
        sWe[i] = We4[i];
    }
    if (threadIdx.x < 64) sb[threadIdx.x] = bias[threadIdx.x];
    __syncthreads();

    int n = blockIdx.x * 128 + threadIdx.x;
    if (n >= Nn) return;

    float acc[64];
#pragma unroll
    for (int j = 0; j < 64; j++) acc[j] = sb[j];

    const float4* xr = xin + (size_t)n * 16;
    const float4* ar = agg + (size_t)n * 16;

    float4 xv = xr[0];
    float4 av = ar[0];
#pragma unroll 1
    for (int kk = 0; kk < 16; kk++) {
        int nxt = (kk + 1) & 15;            // last prefetch wraps (harmless)
        float4 xn = xr[nxt];
        float4 an = ar[nxt];
#pragma unroll
        for (int dk = 0; dk < 4; dk++) {
            float xs = (&xv.x)[dk];
            float as = (&av.x)[dk];
            int k = 4 * kk + dk;
#pragma unroll
            for (int jj = 0; jj < 16; jj++) {
                float4 wv = sWr[k * 16 + jj];
                float4 ev = sWe[k * 16 + jj];
                acc[4 * jj + 0] = fmaf(xs, wv.x, fmaf(as, ev.x, acc[4 * jj + 0]));
                acc[4 * jj + 1] = fmaf(xs, wv.y, fmaf(as, ev.y, acc[4 * jj + 1]));
                acc[4 * jj + 2] = fmaf(xs, wv.z, fmaf(as, ev.z, acc[4 * jj + 2]));
                acc[4 * jj + 3] = fmaf(xs, wv.w, fmaf(as, ev.w, acc[4 * jj + 3]));
            }
        }
        xv = xn;
        av = an;
    }

#pragma unroll
    for (int j = 0; j < 64; j++) {
        float v = acc[j];
        acc[j] = v > 0.f ? v : 0.01f * v;
    }

    if (MODE == 0) {
        float4* o = out + (size_t)n * 16;
#pragma unroll
        for (int jj = 0; jj < 16; jj++)
            o[jj] = make_float4(acc[4 * jj + 0], acc[4 * jj + 1],
                                acc[4 * jj + 2], acc[4 * jj + 3]);
    } else {
        int b = guard_idx(batch[n], NGRAPH);
        float4* pr = g_pool + (size_t)b * 16;
#pragma unroll
        for (int jj = 0; jj < 16; jj++)
            red_add_v4(&pr[jj], make_float4(acc[4 * jj + 0], acc[4 * jj + 1],
                                            acc[4 * jj + 2], acc[4 * jj + 3]));
        red_add_f32(((float*)g_cnt4) + b, 1.0f);
    }
}

// ---------------------------------------------------------------------------
// Final: out[g] = (pool[g] / max(cnt[g],1)) @ Wl + bl     (512 x 64 x 8)
// ---------------------------------------------------------------------------
__global__ void final_kernel(const float* __restrict__ Wl,
                             const float* __restrict__ bl,
                             float* __restrict__ out) {
    __shared__ float sW[64 * 8];
    __shared__ float sb2[8];
    int t = threadIdx.x;                 // blockDim.x == 512
    sW[t] = Wl[t];
    if (t < 8) sb2[t] = bl[t];
    __syncthreads();

    int g = t;
    float cnt = ((const float*)g_cnt4)[g];
    float inv = 1.0f / fmaxf(cnt, 1.0f);
    const float* pr = (const float*)(g_pool + (size_t)g * 16);

    float acc[8];
#pragma unroll
    for (int j = 0; j < 8; j++) acc[j] = sb2[j];
#pragma unroll 4
    for (int k = 0; k < 64; k++) {
        float p = pr[k] * inv;
#pragma unroll
        for (int j = 0; j < 8; j++)
            acc[j] = fmaf(p, sW[k * 8 + j], acc[j]);
    }
#pragma unroll
    for (int j = 0; j < 8; j++) out[g * 8 + j] = acc[j];
}

// ---------------------------------------------------------------------------
// Launch sequence (graph-capturable: kernels only)
// ---------------------------------------------------------------------------
extern "C" void kernel_launch(void* const* d_in, const int* in_sizes, int n_in,
                              void* d_out, int out_size) {
    const float4* x      = (const float4*)d_in[0];
    const int*    ei     = (const int*)d_in[1];     // [2, E] int32
    const float*  w      = (const float*)d_in[2];
    const int*    batch  = (const int*)d_in[3];     // int32
    const float*  W1root = (const float*)d_in[4];
    const float*  W1rel  = (const float*)d_in[5];
    const float*  b1     = (const float*)d_in[6];
    const float*  W2root = (const float*)d_in[7];
    const float*  W2rel  = (const float*)d_in[8];
    const float*  b2     = (const float*)d_in[9];
    const float*  Wl     = (const float*)d_in[10];
    const float*  bl     = (const float*)d_in[11];
    float*        out    = (float*)d_out;

    int N = in_sizes[0] / DIM;        // 100000
    int E = in_sizes[2];              // 1250000
    if (N > NMAX) N = NMAX;
    if (E > EMAX) E = EMAX;
    const int* src = ei;
    const int* dst = ei + E;

    float4 *agg, *h;
    int *off;
    cudaGetSymbolAddress((void**)&agg, g_agg);
    cudaGetSymbolAddress((void**)&h,   g_h);
    cudaGetSymbolAddress((void**)&off, g_off);

    int nb      = (N + SCAN_BLK - 1) / SCAN_BLK;       // 98
    int eBlk    = (E + 255) / 256;
    int nBlk    = (N + 255) / 256;
    int gemmBlk = (N + 127) / 128;
    int aggBlk  = (N + 7) / 8;                         // 8 warps / block

    // ---- CSR build (once; shared by both layers) + all scratch zeroing ----
    init_kernel<<<nBlk, 256>>>(N);
    hist_kernel<<<eBlk, 256>>>(dst, E, N);
    scanA_kernel<<<nb, SCAN_BLK>>>(off, N);
    scanB_kernel<<<1, NB_MAX>>>(nb, off + N, E);
    scanC_kernel<<<nBlk, 256>>>(off, N);
    fill_kernel<<<eBlk, 256>>>(src, dst, w, E, N);

    // ---- Layer 1 ----
    agg_csr_kernel<<<aggBlk, 256>>>(x, agg, N);
    node_gemm_kernel<0><<<gemmBlk, 128>>>(x, agg, W1root, W1rel, b1,
                                          h, nullptr, N);
    // ---- Layer 2 (+ fused mean-pool accumulation) ----
    agg_csr_kernel<<<aggBlk, 256>>>(h, agg, N);
    node_gemm_kernel<1><<<gemmBlk, 128>>>(h, agg, W2root, W2rel, b2,
                                          nullptr, batch, N);
    // ---- Readout ----
    final_kernel<<<1, 512>>>(Wl, bl, out);
}

// round 9
// speedup vs baseline: 2.2057x; 1.1451x over previous
#include <cuda_runtime.h>
#include <cuda_bf16.h>

// Problem constants (dataset fixed; runtime values clamped to these).
#define NMAX   100000
#define EMAX   1250000
#define DIM    64
#define NGRAPH 512
#define SCAN_BLK 1024
#define NB_MAX   128    // ceil(NMAX/SCAN_BLK) = 98 <= 128
#define BPAD   132      // smem row pad for conflict-free tf32 B-frag loads

// ---------------- scratch (__device__ globals; allocation-free rule) -------
__device__ float4 g_agg  [NMAX   * (DIM / 4)];   // 25.6 MB
__device__ float4 g_h    [NMAX   * (DIM / 4)];   // 25.6 MB
__device__ float4 g_pool [NGRAPH * (DIM / 4)];
__device__ float4 g_cnt4 [NGRAPH / 4];
// CSR scratch
__device__ int   g_deg   [NMAX];
__device__ int   g_cursor[NMAX];
__device__ int   g_off   [NMAX + 1];
__device__ int   g_bsum  [NB_MAX];
__device__ int   g_boff  [NB_MAX];
__device__ int   g_psrc  [EMAX];
__device__ float g_pw    [EMAX];

// ---------------------------------------------------------------------------
__device__ __forceinline__ void red_add_v2(float* addr, float a, float b) {
    asm volatile("red.global.add.v2.f32 [%0], {%1, %2};"
                 :: "l"(addr), "f"(a), "f"(b) : "memory");
}
__device__ __forceinline__ void red_add_f32(float* addr, float v) {
    asm volatile("red.global.add.f32 [%0], %1;"
                 :: "l"(addr), "f"(v) : "memory");
}
__device__ __forceinline__ int guard_idx(int i, int n) {
    return ((unsigned)i < (unsigned)n) ? i : 0;
}
__device__ __forceinline__ unsigned f2tf32(float f) {
    unsigned u; asm("cvt.rna.tf32.f32 %0, %1;" : "=r"(u) : "f"(f)); return u;
}
// D += A(16x8,row) * B(8x8,col), tf32 inputs, fp32 accumulate.
__device__ __forceinline__ void mma_tf32(float* d, const unsigned* a,
                                         unsigned b0, unsigned b1) {
    asm volatile(
        "mma.sync.aligned.m16n8k8.row.col.f32.tf32.tf32.f32 "
        "{%0,%1,%2,%3}, {%4,%5,%6,%7}, {%8,%9}, {%0,%1,%2,%3};"
        : "+f"(d[0]), "+f"(d[1]), "+f"(d[2]), "+f"(d[3])
        : "r"(a[0]), "r"(a[1]), "r"(a[2]), "r"(a[3]), "r"(b0), "r"(b1));
}

// ---------------------------------------------------------------------------
// Degree histogram (deg is zeroed by the PREVIOUS replay's scanA; first call
// relies on static zero-init of __device__ globals).
// ---------------------------------------------------------------------------
__global__ void hist_kernel(const int* __restrict__ dst, int E, int N) {
    int e = blockIdx.x * blockDim.x + threadIdx.x;
    if (e < E) atomicAdd(&g_deg[guard_idx(dst[e], N)], 1);
}

// ---------------------------------------------------------------------------
// 3-phase exclusive scan (dependency depth = 3 kernels). scanA zeroes deg
// after reading it (feeds the next graph replay). scanC seeds cursor.
// ---------------------------------------------------------------------------
__global__ void scanA_kernel(int* __restrict__ off, int N) {
    __shared__ int s[SCAN_BLK];
    int tx = threadIdx.x;
    int i = blockIdx.x * SCAN_BLK + tx;
    int v = (i < N) ? g_deg[i] : 0;
    if (i < N) g_deg[i] = 0;                       // reset for next replay
    s[tx] = v;
    __syncthreads();
    for (int d = 1; d < SCAN_BLK; d <<= 1) {
        int t = (tx >= d) ? s[tx - d] : 0;
        __syncthreads();
        s[tx] += t;
        __syncthreads();
    }
    if (i < N) off[i] = s[tx] - v;
    if (tx == SCAN_BLK - 1) g_bsum[blockIdx.x] = s[tx];
}

__global__ void scanB_kernel(int nb, int* __restrict__ off_last, int E) {
    __shared__ int s[NB_MAX];
    int tx = threadIdx.x;                          // blockDim.x == NB_MAX
    int v = (tx < nb) ? g_bsum[tx] : 0;
    s[tx] = v;
    __syncthreads();
    for (int d = 1; d < NB_MAX; d <<= 1) {
        int t = (tx >= d) ? s[tx - d] : 0;
        __syncthreads();
        s[tx] += t;
        __syncthreads();
    }
    if (tx < nb) g_boff[tx] = s[tx] - v;
    if (tx == 0) *off_last = E;                    // off[N] = E
}

__global__ void scanC_kernel(int* __restrict__ off, int N) {
    int i = blockIdx.x * blockDim.x + threadIdx.x;
    if (i < N) {
        int o = off[i] + g_boff[i >> 10];
        off[i] = o;
        g_cursor[i] = o;        // seed cursor: fill needs only one atomicAdd
    }
}

// ---------------------------------------------------------------------------
// Bucket fill: one atomicAdd on the pre-seeded cursor gives the slot.
// ---------------------------------------------------------------------------
__global__ void fill_kernel(const int* __restrict__ src, const int* __restrict__ dst,
                            const float* __restrict__ w, int E, int N) {
    int e = blockIdx.x * blockDim.x + threadIdx.x;
    if (e >= E) return;
    int d = guard_idx(dst[e], N);
    int slot = atomicAdd(&g_cursor[d], 1);
    g_psrc[slot] = guard_idx(src[e], N);
    g_pw[slot]   = w[e];
}

// ---------------------------------------------------------------------------
// CSR aggregation: one warp per dst row; half-warp h walks edges beg+h,
// beg+h+2, ...; lane j owns float4 column j (256B coalesced gather/edge).
// ---------------------------------------------------------------------------
__global__ __launch_bounds__(256)
void agg_csr_kernel(const float4* __restrict__ feat,
                    float4* __restrict__ agg, int N) {
    int warp = (blockIdx.x * blockDim.x + threadIdx.x) >> 5;
    if (warp >= N) return;
    int lane = threadIdx.x & 31;
    int half = lane >> 4;
    int j = lane & 15;

    int beg = g_off[warp];
    int end = g_off[warp + 1];

    float4 a0 = make_float4(0.f, 0.f, 0.f, 0.f);
    float4 a1 = make_float4(0.f, 0.f, 0.f, 0.f);
    int i = beg + half;
    for (; i + 2 < end; i += 4) {
        int   s0 = g_psrc[i],  s1 = g_psrc[i + 2];
        float w0 = g_pw[i],    w1 = g_pw[i + 2];
        float4 v0 = feat[(size_t)s0 * 16 + j];
        float4 v1 = feat[(size_t)s1 * 16 + j];
        a0.x = fmaf(v0.x, w0, a0.x);  a1.x = fmaf(v1.x, w1, a1.x);
        a0.y = fmaf(v0.y, w0, a0.y);  a1.y = fmaf(v1.y, w1, a1.y);
        a0.z = fmaf(v0.z, w0, a0.z);  a1.z = fmaf(v1.z, w1, a1.z);
        a0.w = fmaf(v0.w, w0, a0.w);  a1.w = fmaf(v1.w, w1, a1.w);
    }
    if (i < end) {
        int   s0 = g_psrc[i];
        float w0 = g_pw[i];
        float4 v0 = feat[(size_t)s0 * 16 + j];
        a0.x = fmaf(v0.x, w0, a0.x);
        a0.y = fmaf(v0.y, w0, a0.y);
        a0.z = fmaf(v0.z, w0, a0.z);
        a0.w = fmaf(v0.w, w0, a0.w);
    }
    a0.x += a1.x; a0.y += a1.y; a0.z += a1.z; a0.w += a1.w;
    a0.x += __shfl_xor_sync(0xffffffffu, a0.x, 16);
    a0.y += __shfl_xor_sync(0xffffffffu, a0.y, 16);
    a0.z += __shfl_xor_sync(0xffffffffu, a0.z, 16);
    a0.w += __shfl_xor_sync(0xffffffffu, a0.w, 16);
    if (half == 0) agg[(size_t)warp * 16 + j] = a0;
}

// ---------------------------------------------------------------------------
// Tensor-core node transform (3xTF32 for fp32-level accuracy):
//   out = leaky_relu( [x | agg] @ [Wroot ; Wrel] + b )
// One warp = 16 nodes (rows). K = 128 (64 from x, 64 from agg), cols = 64.
// mma.sync.m16n8k8.tf32: per k-tile, 8 n-tiles x 3 terms (AhiBhi + AhiBlo +
// AloBhi). Weights (hi/lo tf32 split) live in padded dynamic smem,
// [64 n][BPAD k] so b-frag loads are bank-conflict-free.
// MODE 0: store rows. MODE 1: fused mean-pool (red.v2 into pool by graph id).
// ---------------------------------------------------------------------------
template <int MODE>
__global__ __launch_bounds__(128)
void node_mma_kernel(const float* __restrict__ xin,
                     const float* __restrict__ agg,
                     const float* __restrict__ Wroot,
                     const float* __restrict__ Wrel,
                     const float* __restrict__ bias,
                     float* __restrict__ out,
                     const int* __restrict__ batch,
                     int Nn) {
    extern __shared__ float smem[];
    float* sBhi = smem;                    // [64][BPAD]
    float* sBlo = smem + 64 * BPAD;        // [64][BPAD]
    float* sb   = smem + 2 * 64 * BPAD;    // [64]

    int tid = threadIdx.x;
    for (int idx = tid; idx < 128 * 64; idx += 128) {
        int k = idx >> 6, n = idx & 63;
        float w = (k < 64) ? Wroot[k * 64 + n] : Wrel[(k - 64) * 64 + n];
        float hi = __uint_as_float(f2tf32(w));      // tf32 bits are valid fp32
        sBhi[n * BPAD + k] = hi;
        sBlo[n * BPAD + k] = __uint_as_float(f2tf32(w - hi));
    }
    if (tid < 64) sb[tid] = bias[tid];
    __syncthreads();

    int warp = (blockIdx.x * blockDim.x + tid) >> 5;
    if (warp >= (Nn + 15) >> 4) return;
    int lane = tid & 31;
    int g = lane >> 2;          // group id (0..7)
    int t = lane & 3;           // thread-in-group (0..3)

    int r0 = warp * 16 + g;
    int r1 = r0 + 8;
    int r0c = r0 < Nn ? r0 : Nn - 1;
    int r1c = r1 < Nn ? r1 : Nn - 1;

    // C fragments: acc[nt*4 + {0,1}] = D[r0][nt*8+2t, +1]; {2,3} = row r1.
    float acc[32];
#pragma unroll
    for (int nt = 0; nt < 8; nt++) {
        float bb0 = sb[nt * 8 + 2 * t];
        float bb1 = sb[nt * 8 + 2 * t + 1];
        acc[nt * 4 + 0] = bb0; acc[nt * 4 + 1] = bb1;
        acc[nt * 4 + 2] = bb0; acc[nt * 4 + 3] = bb1;
    }

    const float* x0 = xin + (size_t)r0c * 64;
    const float* x1 = xin + (size_t)r1c * 64;
    const float* a0p = agg + (size_t)r0c * 64 - 64;   // pre-biased for k>=64
    const float* a1p = agg + (size_t)r1c * 64 - 64;

#pragma unroll 1
    for (int kt = 0; kt < 16; kt++) {
        int k0 = kt * 8 + t;          // k0 < 64  <=>  kt < 8 (uniform)
        int k1 = k0 + 4;
        const float* p0 = (kt < 8) ? x0 : a0p;
        const float* p1 = (kt < 8) ? x1 : a1p;
        float v0 = p0[k0];            // A[r0][k0]
        float v1 = p1[k0];            // A[r1][k0]
        float v2 = p0[k1];            // A[r0][k1]
        float v3 = p1[k1];            // A[r1][k1]

        unsigned ahi[4], alo[4];
        ahi[0] = f2tf32(v0); alo[0] = f2tf32(v0 - __uint_as_float(ahi[0]));
        ahi[1] = f2tf32(v1); alo[1] = f2tf32(v1 - __uint_as_float(ahi[1]));
        ahi[2] = f2tf32(v2); alo[2] = f2tf32(v2 - __uint_as_float(ahi[2]));
        ahi[3] = f2tf32(v3); alo[3] = f2tf32(v3 - __uint_as_float(ahi[3]));

#pragma unroll
        for (int nt = 0; nt < 8; nt++) {
            int bbase = (nt * 8 + g) * BPAD + k0;
            unsigned bh0 = __float_as_uint(sBhi[bbase]);
            unsigned bh1 = __float_as_uint(sBhi[bbase + 4]);
            unsigned bl0 = __float_as_uint(sBlo[bbase]);
            unsigned bl1 = __float_as_uint(sBlo[bbase + 4]);
            mma_tf32(acc + nt * 4, ahi, bh0, bh1);
            mma_tf32(acc + nt * 4, ahi, bl0, bl1);
            mma_tf32(acc + nt * 4, alo, bh0, bh1);
        }
    }

#pragma unroll
    for (int i2 = 0; i2 < 32; i2++) {
        float v = acc[i2];
        acc[i2] = v > 0.f ? v : 0.01f * v;          // leaky relu
    }

    if (MODE == 0) {
        if (r0 < Nn) {
            float2* o = (float2*)(out + (size_t)r0 * 64);
#pragma unroll
            for (int nt = 0; nt < 8; nt++)
                o[nt * 4 + t] = make_float2(acc[nt * 4 + 0], acc[nt * 4 + 1]);
        }
        if (r1 < Nn) {
            float2* o = (float2*)(out + (size_t)r1 * 64);
#pragma unroll
            for (int nt = 0; nt < 8; nt++)
                o[nt * 4 + t] = make_float2(acc[nt * 4 + 2], acc[nt * 4 + 3]);
        }
    } else {
        float* pool = (float*)g_pool;
        float* cnt  = (float*)g_cnt4;
        if (r0 < Nn) {
            int b = guard_idx(batch[r0], NGRAPH);
            float* pr = pool + (size_t)b * 64;
#pragma unroll
            for (int nt = 0; nt < 8; nt++)
                red_add_v2(pr + nt * 8 + 2 * t, acc[nt * 4 + 0], acc[nt * 4 + 1]);
            if (t == 0) red_add_f32(cnt + b, 1.0f);
        }
        if (r1 < Nn) {
            int b = guard_idx(batch[r1], NGRAPH);
            float* pr = pool + (size_t)b * 64;
#pragma unroll
            for (int nt = 0; nt < 8; nt++)
                red_add_v2(pr + nt * 8 + 2 * t, acc[nt * 4 + 2], acc[nt * 4 + 3]);
            if (t == 0) red_add_f32(cnt + b, 1.0f);
        }
    }
}

// ---------------------------------------------------------------------------
// Final: out[g] = (pool[g] / max(cnt[g],1)) @ Wl + bl     (512 x 64 x 8)
// Also zeroes pool/cnt after reading (feeds the next graph replay).
// ---------------------------------------------------------------------------
__global__ void final_kernel(const float* __restrict__ Wl,
                             const float* __restrict__ bl,
                             float* __restrict__ out) {
    __shared__ float sW[64 * 8];
    __shared__ float sb2[8];
    int t = threadIdx.x;                 // blockDim.x == 512
    sW[t] = Wl[t];
    if (t < 8) sb2[t] = bl[t];
    __syncthreads();

    int g = t;
    float* cnt = (float*)g_cnt4;
    float inv = 1.0f / fmaxf(cnt[g], 1.0f);
    float* pr = (float*)(g_pool + (size_t)g * 16);

    float acc[8];
#pragma unroll
    for (int j = 0; j < 8; j++) acc[j] = sb2[j];
#pragma unroll 4
    for (int k = 0; k < 64; k++) {
        float p = pr[k] * inv;
#pragma unroll
        for (int j = 0; j < 8; j++)
            acc[j] = fmaf(p, sW[k * 8 + j], acc[j]);
    }
#pragma unroll
    for (int j = 0; j < 8; j++) out[g * 8 + j] = acc[j];

    // reset pool scratch for next replay
#pragma unroll 4
    for (int k = 0; k < 64; k++) pr[k] = 0.f;
    cnt[g] = 0.f;
}

// ---------------------------------------------------------------------------
// Launch sequence (graph-capturable: kernels only)
// ---------------------------------------------------------------------------
extern "C" void kernel_launch(void* const* d_in, const int* in_sizes, int n_in,
                              void* d_out, int out_size) {
    const float4* x      = (const float4*)d_in[0];
    const int*    ei     = (const int*)d_in[1];     // [2, E] int32
    const float*  w      = (const float*)d_in[2];
    const int*    batch  = (const int*)d_in[3];     // int32
    const float*  W1root = (const float*)d_in[4];
    const float*  W1rel  = (const float*)d_in[5];
    const float*  b1     = (const float*)d_in[6];
    const float*  W2root = (const float*)d_in[7];
    const float*  W2rel  = (const float*)d_in[8];
    const float*  b2     = (const float*)d_in[9];
    const float*  Wl     = (const float*)d_in[10];
    const float*  bl     = (const float*)d_in[11];
    float*        out    = (float*)d_out;

    int N = in_sizes[0] / DIM;        // 100000
    int E = in_sizes[2];              // 1250000
    if (N > NMAX) N = NMAX;
    if (E > EMAX) E = EMAX;
    const int* src = ei;
    const int* dst = ei + E;

    float4 *agg, *h;
    int *off;
    cudaGetSymbolAddress((void**)&agg, g_agg);
    cudaGetSymbolAddress((void**)&h,   g_h);
    cudaGetSymbolAddress((void**)&off, g_off);

    int nb     = (N + SCAN_BLK - 1) / SCAN_BLK;        // 98
    int eBlk   = (E + 255) / 256;
    int nBlk   = (N + 255) / 256;
    int aggBlk = (N + 7) / 8;                          // 8 warps / block
    int mmaBlk = (((N + 15) / 16) + 3) / 4;            // 4 warps (16 nodes ea)

    const int SMEM_MMA = (2 * 64 * BPAD + 64) * sizeof(float);   // 67840 B
    cudaFuncSetAttribute(node_mma_kernel<0>,
                         cudaFuncAttributeMaxDynamicSharedMemorySize, SMEM_MMA);
    cudaFuncSetAttribute(node_mma_kernel<1>,
                         cudaFuncAttributeMaxDynamicSharedMemorySize, SMEM_MMA);

    // ---- CSR build (once; shared by both layers) ----
    hist_kernel<<<eBlk, 256>>>(dst, E, N);
    scanA_kernel<<<nb, SCAN_BLK>>>(off, N);
    scanB_kernel<<<1, NB_MAX>>>(nb, off + N, E);
    scanC_kernel<<<nBlk, 256>>>(off, N);
    fill_kernel<<<eBlk, 256>>>(src, dst, w, E, N);

    // ---- Layer 1 ----
    agg_csr_kernel<<<aggBlk, 256>>>(x, agg, N);
    node_mma_kernel<0><<<mmaBlk, 128, SMEM_MMA>>>((const float*)x, (const float*)agg,
                                                  W1root, W1rel, b1,
                                                  (float*)h, nullptr, N);
    // ---- Layer 2 (+ fused mean-pool accumulation) ----
    agg_csr_kernel<<<aggBlk, 256>>>(h, agg, N);
    node_mma_kernel<1><<<mmaBlk, 128, SMEM_MMA>>>((const float*)h, (const float*)agg,
                                                  W2root, W2rel, b2,
                                                  nullptr, batch, N);
    // ---- Readout ----
    final_kernel<<<1, 512>>>(Wl, bl, out);
}